// round 1
// baseline (speedup 1.0000x reference)
#include <cuda_runtime.h>
#include <cstdint>
#include <cstddef>

#define NNODE 1500
#define T_IN  168
#define TLEN  162
#define BATCH 8
#define CH    16
#define EMBD  16
#define KTOP  12
#define NBRS  13            // KTOP + self
#define FDIM  (BATCH*CH*TLEN)   // 20736
#define ALPHA 1.5f
#define BETA  0.2f

// ---------------- device scratch (no allocations allowed) ----------------
__device__ float g_H0[(size_t)NNODE * FDIM];
__device__ float g_H1[(size_t)NNODE * FDIM];
__device__ float g_H2[(size_t)NNODE * FDIM];
__device__ float g_m1[NNODE * EMBD];
__device__ float g_m2[NNODE * EMBD];
__device__ float g_weff[CH * 8];
__device__ float g_beff[CH];
__device__ int   g_nbr[NNODE * NBRS];
__device__ float g_nw [NNODE * NBRS];

// ---------------- constant weights for the MLP head ----------------
__constant__ float c_mw [16 * 48];
__constant__ float c_mb [16];
__constant__ float c_rw1[16 * 16];
__constant__ float c_rb1[16];
__constant__ float c_rw2[24 * 16];
__constant__ float c_rb2[24];

// ============ K0a: fold pw/pb into the inception conv weights ============
__global__ void k_prep_weff(const float* pw, const float* pb,
                            const float* tw2, const float* tb2,
                            const float* tw3, const float* tb3,
                            const float* tw6, const float* tb6,
                            const float* tw7, const float* tb7) {
    int c = threadIdx.x;
    if (c >= CH) return;
    int br = c >> 2, o = c & 3;
    const float* tw; const float* tb; int k;
    if      (br == 0) { tw = tw2; tb = tb2; k = 2; }
    else if (br == 1) { tw = tw3; tb = tb3; k = 3; }
    else if (br == 2) { tw = tw6; tb = tb6; k = 6; }
    else              { tw = tw7; tb = tb7; k = 7; }
    float bacc = tb[o];
    for (int j = 0; j < k; j++) {
        float wacc = 0.f;
        for (int ci = 0; ci < CH; ci++) {
            float w = tw[(o * CH + ci) * k + j];
            wacc += w * pw[ci];
            bacc += w * pb[ci];
        }
        g_weff[c * 8 + j] = wacc;
    }
    g_beff[c] = bacc;
}

// ============ K0b: node embeddings -> m1, m2 ============
__global__ void k_prep_m(const float* e1, const float* gw1, const float* gb1,
                         const float* e2, const float* gw2, const float* gb2) {
    int n = blockIdx.x * blockDim.x + threadIdx.x;
    if (n >= NNODE) return;
    float ev1[EMBD], ev2[EMBD];
#pragma unroll
    for (int i = 0; i < EMBD; i++) { ev1[i] = e1[n * EMBD + i]; ev2[i] = e2[n * EMBD + i]; }
#pragma unroll
    for (int e = 0; e < EMBD; e++) {
        float a1 = gb1[e], a2 = gb2[e];
#pragma unroll
        for (int k = 0; k < EMBD; k++) {
            a1 += ev1[k] * gw1[k * EMBD + e];
            a2 += ev2[k] * gw2[k * EMBD + e];
        }
        g_m1[n * EMBD + e] = tanhf(ALPHA * a1);
        g_m2[n * EMBD + e] = tanhf(ALPHA * a2);
    }
}

// ============ K1: per-row scores + iterative top-12 + row-normalize ============
__global__ void k_topk() {
    int v = blockIdx.x;
    int tid = threadIdx.x;
    __shared__ float s[NNODE];
    __shared__ float rv[256];
    __shared__ int   ri[256];
    __shared__ float selv[KTOP];

    float m1v[EMBD], m2v[EMBD];
#pragma unroll
    for (int e = 0; e < EMBD; e++) { m1v[e] = g_m1[v * EMBD + e]; m2v[e] = g_m2[v * EMBD + e]; }

    for (int w = tid; w < NNODE; w += 256) {
        float d = 0.f;
#pragma unroll
        for (int e = 0; e < EMBD; e++)
            d += m1v[e] * g_m2[w * EMBD + e] - m2v[e] * g_m1[w * EMBD + e];
        float a = tanhf(ALPHA * d);
        s[w] = a > 0.f ? a : 0.f;
    }
    __syncthreads();

    for (int it = 0; it < KTOP; it++) {
        float best = -1.f; int bi = NNODE;
        for (int w = tid; w < NNODE; w += 256) {
            float val = s[w];
            if (val > best || (val == best && w < bi)) { best = val; bi = w; }
        }
        rv[tid] = best; ri[tid] = bi;
        __syncthreads();
        for (int off = 128; off; off >>= 1) {
            if (tid < off) {
                if (rv[tid + off] > rv[tid] ||
                    (rv[tid + off] == rv[tid] && ri[tid + off] < ri[tid])) {
                    rv[tid] = rv[tid + off]; ri[tid] = ri[tid + off];
                }
            }
            __syncthreads();
        }
        if (tid == 0) {
            int bw = ri[0];
            selv[it] = rv[0];
            g_nbr[v * NBRS + it] = bw;
            s[bw] = -2.f;
        }
        __syncthreads();
    }
    if (tid == 0) {
        float rs = 1.f;                       // + identity
        for (int i = 0; i < KTOP; i++) rs += selv[i];
        float inv = 1.f / rs;
        for (int i = 0; i < KTOP; i++) g_nw[v * NBRS + i] = selv[i] * inv;
        g_nbr[v * NBRS + KTOP] = v;
        g_nw [v * NBRS + KTOP] = inv;         // self (identity) weight
    }
}

// ============ K2: folded inception temporal conv -> H0[N][F] ============
__global__ void k_tconv(const float* __restrict__ x) {
    int n = blockIdx.x;
    int tid = threadIdx.x;
    __shared__ float xs[BATCH][T_IN];
    __shared__ float sw[CH][8];
    __shared__ float sb[CH];
    for (int i = tid; i < BATCH * T_IN; i += 256) {
        int b = i / T_IN, t = i % T_IN;
        xs[b][t] = x[((size_t)b * T_IN + t) * NNODE + n];
    }
    if (tid < CH * 8) sw[tid >> 3][tid & 7] = g_weff[tid];
    if (tid < CH)     sb[tid] = g_beff[tid];
    __syncthreads();

    float* out = g_H0 + (size_t)n * FDIM;
    for (int f = tid; f < FDIM; f += 256) {
        int t  = f % TLEN;
        int bc = f / TLEN;
        int c  = bc & 15;
        int b  = bc >> 4;
        int k  = c < 4 ? 2 : (c < 8 ? 3 : (c < 12 ? 6 : 7));
        int base = t + 7 - k;
        float acc = sb[c];
        for (int j = 0; j < k; j++) acc += sw[c][j] * xs[b][base + j];
        out[f] = fmaxf(acc, 0.f);
    }
}

// ============ K3/K4: sparse mixprop hop (13 nnz/row SpMM) ============
__global__ void k_spmm(int hop) {
    int v = blockIdx.x;
    int f = blockIdx.y * 256 + threadIdx.x;
    __shared__ int   nb[NBRS];
    __shared__ float nw[NBRS];
    if (threadIdx.x < NBRS) {
        nb[threadIdx.x] = g_nbr[v * NBRS + threadIdx.x];
        nw[threadIdx.x] = g_nw [v * NBRS + threadIdx.x];
    }
    __syncthreads();
    const float* src = hop ? g_H1 : g_H0;
    float acc = 0.f;
#pragma unroll
    for (int i = 0; i < NBRS; i++)
        acc += nw[i] * src[(size_t)nb[i] * FDIM + f];
    float h0v = g_H0[(size_t)v * FDIM + f];
    float* dst = hop ? g_H2 : g_H1;
    dst[(size_t)v * FDIM + f] = BETA * h0v + (1.f - BETA) * acc;
}

// ============ K5: MLP head (48->16 relu ->16 relu), time-mean, 16->24 ============
__global__ void k_final(float* __restrict__ out) {
    int v = blockIdx.x;
    int b = blockIdx.y;
    int tid = threadIdx.x;
    bool valid = tid < TLEN;
    int t = valid ? tid : 0;

    size_t base = (size_t)v * FDIM + (size_t)(b * CH) * TLEN + t;
    float ho[48];
#pragma unroll
    for (int c = 0; c < CH; c++) {
        ho[c]      = g_H0[base + (size_t)c * TLEN];
        ho[16 + c] = g_H1[base + (size_t)c * TLEN];
        ho[32 + c] = g_H2[base + (size_t)c * TLEN];
    }
    float z[16];
#pragma unroll
    for (int j = 0; j < 16; j++) {
        float a = c_mb[j];
#pragma unroll
        for (int c = 0; c < 48; c++) a += c_mw[j * 48 + c] * ho[c];
        z[j] = fmaxf(a, 0.f);
    }
    float r[16];
#pragma unroll
    for (int i = 0; i < 16; i++) {
        float a = c_rb1[i];
#pragma unroll
        for (int j = 0; j < 16; j++) a += c_rw1[i * 16 + j] * z[j];
        r[i] = valid ? fmaxf(a, 0.f) : 0.f;
    }

    // block-reduce sum over t
    __shared__ float part[6][16];
    __shared__ float rm[16];
    int warp = tid >> 5, lane = tid & 31;
#pragma unroll
    for (int c = 0; c < 16; c++) {
        float s = r[c];
#pragma unroll
        for (int off = 16; off; off >>= 1) s += __shfl_xor_sync(0xffffffffu, s, off);
        if (lane == 0) part[warp][c] = s;
    }
    __syncthreads();
    if (tid < 16) {
        float s = 0.f;
#pragma unroll
        for (int w = 0; w < 6; w++) s += part[w][tid];
        rm[tid] = s * (1.f / (float)TLEN);
    }
    __syncthreads();
    if (tid < 24) {
        float a = c_rb2[tid];
#pragma unroll
        for (int c = 0; c < 16; c++) a += c_rw2[tid * 16 + c] * rm[c];
        out[((size_t)b * 24 + tid) * NNODE + v] = a;
    }
}

// ======================= launcher =======================
extern "C" void kernel_launch(void* const* d_in, const int* in_sizes, int n_in,
                              void* d_out, int out_size) {
    const float* x   = (const float*)d_in[0];
    const float* pw  = (const float*)d_in[1];
    const float* pb  = (const float*)d_in[2];
    const float* tw2 = (const float*)d_in[3];
    const float* tb2 = (const float*)d_in[4];
    const float* tw3 = (const float*)d_in[5];
    const float* tb3 = (const float*)d_in[6];
    const float* tw6 = (const float*)d_in[7];
    const float* tb6 = (const float*)d_in[8];
    const float* tw7 = (const float*)d_in[9];
    const float* tb7 = (const float*)d_in[10];
    const float* e1  = (const float*)d_in[11];
    const float* e2  = (const float*)d_in[12];
    const float* gw1 = (const float*)d_in[13];
    const float* gb1 = (const float*)d_in[14];
    const float* gw2 = (const float*)d_in[15];
    const float* gb2 = (const float*)d_in[16];

    // MLP head weights -> constant bank (D2D async copies are capture-legal)
    cudaMemcpyToSymbolAsync(c_mw,  d_in[17], 16 * 48 * sizeof(float), 0, cudaMemcpyDeviceToDevice, 0);
    cudaMemcpyToSymbolAsync(c_mb,  d_in[18], 16 * sizeof(float),      0, cudaMemcpyDeviceToDevice, 0);
    cudaMemcpyToSymbolAsync(c_rw1, d_in[19], 16 * 16 * sizeof(float), 0, cudaMemcpyDeviceToDevice, 0);
    cudaMemcpyToSymbolAsync(c_rb1, d_in[20], 16 * sizeof(float),      0, cudaMemcpyDeviceToDevice, 0);
    cudaMemcpyToSymbolAsync(c_rw2, d_in[21], 24 * 16 * sizeof(float), 0, cudaMemcpyDeviceToDevice, 0);
    cudaMemcpyToSymbolAsync(c_rb2, d_in[22], 24 * sizeof(float),      0, cudaMemcpyDeviceToDevice, 0);

    k_prep_weff<<<1, 32>>>(pw, pb, tw2, tb2, tw3, tb3, tw6, tb6, tw7, tb7);
    k_prep_m<<<(NNODE + 127) / 128, 128>>>(e1, gw1, gb1, e2, gw2, gb2);
    k_topk<<<NNODE, 256>>>();
    k_tconv<<<NNODE, 256>>>(x);

    dim3 gs(NNODE, FDIM / 256);   // 1500 x 81
    k_spmm<<<gs, 256>>>(0);
    k_spmm<<<gs, 256>>>(1);

    dim3 gf(NNODE, BATCH);        // 1500 x 8
    k_final<<<gf, 192>>>((float*)d_out);
}